// round 14
// baseline (speedup 1.0000x reference)
#include <cuda_runtime.h>
#include <cuda_bf16.h>
#include <math.h>

// ---------------------------------------------------------------------------
// Llama-style decode step, BATCH=8, S=1. R13-champion + R14 fusions:
//  - attn_combine folded into wo X-staging (XSEL=1)
//  - finish_norm folded into w13/wout X-staging (XSEL=3)
// GEMVs: f32x2 FMA, 4 cols/thread, 256 thr, (256,4) bounds, unroll-8,
// .cs weights only. Attention: ACH=256 single wave, ILP-4 score pass.
// ---------------------------------------------------------------------------

#define DM 4096
#define NH 32
#define NKV 8
#define HD 128
#define HID 14336
#define VOC 32000
#define MSEQ 2048
#define B8 8
#define ACH 256   // attention chunk length
#define NCHK 8    // MSEQ / ACH

// ------------------------- scratch (device globals) -------------------------
__device__ float g_h[B8 * DM];
__device__ float g_xn[B8 * DM];
__device__ float g_xq[B8 * NH * HD];
__device__ float g_xk[B8 * NKV * HD];
__device__ float g_xv[B8 * NKV * HD];
__device__ float g_pm[B8 * NH * NCHK];
__device__ float g_pl[B8 * NH * NCHK];
__device__ float g_po[B8 * NH * NCHK * HD];
__device__ float g_g[B8 * HID];
__device__ float g_bsq[B8 * 16];
__device__ float g_PA[16 * 8 * 32000];
__device__ float g_PB[16 * 8 * 14336];

// ------------------------- helpers -------------------------
__device__ __forceinline__ void fma4(float4& a, float s, const float4& w) {
    a.x = fmaf(s, w.x, a.x);
    a.y = fmaf(s, w.y, a.y);
    a.z = fmaf(s, w.z, a.z);
    a.w = fmaf(s, w.w, a.w);
}

__device__ __forceinline__ unsigned long long dup_f32(float v) {
    unsigned long long pv;
    asm("mov.b64 %0, {%1, %1};" : "=l"(pv) : "f"(v));
    return pv;
}

// -------- GEMM inner macro: 1 LDG.128(.cs) + 4 LDS.128 + 16 FFMA2 per k -----
#define GEMM_KSTEP(wp, stride)                                                 \
    {                                                                          \
        ulonglong2 w2;                                                         \
        asm("ld.global.cs.v2.u64 {%0,%1}, [%2];"                               \
            : "=l"(w2.x), "=l"(w2.y) : "l"(wp));                               \
        (wp) += (stride);                                                      \
        _Pragma("unroll") for (int p = 0; p < 4; ++p) {                        \
            ulonglong2 xp = *(const ulonglong2*)&xs[kk][2 * p];                \
            asm("fma.rn.f32x2 %0, %4, %6, %0;\n\t"                             \
                "fma.rn.f32x2 %1, %4, %7, %1;\n\t"                             \
                "fma.rn.f32x2 %2, %5, %6, %2;\n\t"                             \
                "fma.rn.f32x2 %3, %5, %7, %3;"                                 \
                : "+l"(a01[2 * p]), "+l"(a23[2 * p]),                          \
                  "+l"(a01[2 * p + 1]), "+l"(a23[2 * p + 1])                   \
                : "l"(xp.x), "l"(xp.y), "l"(w2.x), "l"(w2.y));                 \
        }                                                                      \
    }

// ------------------------- kernel 0: embed + rmsnorm(gamma1) ----------------
__global__ void embed_norm(const int* __restrict__ tokens,
                           const float* __restrict__ emb,
                           const float* __restrict__ gamma) {
    __shared__ float red[8];
    int b = blockIdx.x;
    int tok = tokens[b];
    const float* row = emb + (size_t)tok * DM;
    float loc[16];
    float sq = 0.f;
#pragma unroll
    for (int i = 0; i < 16; ++i) {
        float v = row[threadIdx.x + i * 256];
        loc[i] = v;
        sq += v * v;
    }
    int lane = threadIdx.x & 31, wid = threadIdx.x >> 5;
#pragma unroll
    for (int o = 16; o; o >>= 1) sq += __shfl_xor_sync(0xffffffffu, sq, o);
    if (!lane) red[wid] = sq;
    __syncthreads();
    float tot = 0.f;
#pragma unroll
    for (int w = 0; w < 8; ++w) tot += red[w];
    float rn = rsqrtf(tot * (1.0f / DM));
#pragma unroll
    for (int i = 0; i < 16; ++i) {
        int c = threadIdx.x + i * 256;
        g_h[b * DM + c] = loc[i];
        g_xn[b * DM + c] = loc[i] * rn * gamma[c];
    }
}

// ------------------------- generic split-K GEMM (M=8), f32x2 ----------------
// XSEL: 0 = g_xn, 1 = fused attention chunk-combine, 2 = g_g,
//       3 = rmsnorm(g_h)*gamma inline (uses g_bsq).
// PSEL: 0 = g_PA, 1 = g_PB.
template <int XSEL, int PSEL, int KCH>
__global__ __launch_bounds__(256, 4) void gemm8(const float* __restrict__ W,
                                                const float* __restrict__ gamma,
                                                int K, int N) {
    float* P = (PSEL == 0) ? g_PA : g_PB;

    __shared__ __align__(16) unsigned long long xs[KCH][8];

    int k0 = blockIdx.y * KCH;
    if (XSEL == 1) {
        // fused attention chunk-combine: X[b][k] = sum_c w_c*po / sum_c w_c*pl
        for (int i = threadIdx.x; i < KCH * 8; i += 256) {
            int kk = i >> 3, b = i & 7;
            int k = k0 + kk;
            int h = k >> 7, d = k & 127;
            int base = ((b << 5) + h) << 3;
            float M = -1e30f;
#pragma unroll
            for (int c = 0; c < NCHK; ++c) M = fmaxf(M, g_pm[base + c]);
            float Ls = 0.f, o = 0.f;
#pragma unroll
            for (int c = 0; c < NCHK; ++c) {
                float wgt = expf(g_pm[base + c] - M);
                Ls += g_pl[base + c] * wgt;
                o += g_po[(size_t)(base + c) * HD + d] * wgt;
            }
            xs[kk][b] = dup_f32(o / Ls);
        }
    } else if (XSEL == 3) {
        int bb = threadIdx.x & 7;
        float sq = 0.f;
#pragma unroll
        for (int i = 0; i < 16; ++i) sq += g_bsq[bb * 16 + i];
        float rn = rsqrtf(sq * (1.0f / DM));
        for (int i = threadIdx.x; i < KCH * 8; i += 256) {
            int kk = i >> 3;
            xs[kk][bb] = dup_f32(g_h[bb * K + k0 + kk] * rn * gamma[k0 + kk]);
        }
    } else {
        const float* X = (XSEL == 0) ? g_xn : g_g;
        for (int i = threadIdx.x; i < KCH * 8; i += 256) {
            int kk = i >> 3, b = i & 7;
            xs[kk][b] = dup_f32(X[b * K + k0 + kk]);
        }
    }
    __syncthreads();

    int n0 = blockIdx.x * 1024 + threadIdx.x * 4;
    if (n0 >= N) return;

    unsigned long long a01[8], a23[8];
#pragma unroll
    for (int b = 0; b < 8; ++b) { a01[b] = 0ull; a23[b] = 0ull; }

    const float* wp = W + (size_t)k0 * N + n0;
#pragma unroll 8
    for (int kk = 0; kk < KCH; ++kk) GEMM_KSTEP(wp, N);

#pragma unroll
    for (int b = 0; b < 8; ++b) {
        ulonglong2 o;
        o.x = a01[b];
        o.y = a23[b];
        *(ulonglong2*)(P + ((size_t)blockIdx.y * 8 + b) * N + n0) = o;
    }
}

// ------------------------- fused QKV GEMM (concat N=6144) -------------------
__global__ __launch_bounds__(256, 4) void gemm_qkv(const float* __restrict__ wq,
                                                   const float* __restrict__ wk,
                                                   const float* __restrict__ wv) {
    const int KCH = 64;   // KS=64 -> 384 blocks
    __shared__ __align__(16) unsigned long long xs[KCH][8];
    const int K = DM;
    int k0 = blockIdx.y * KCH;
    for (int i = threadIdx.x; i < KCH * 8; i += 256) {
        int kk = i >> 3, b = i & 7;
        xs[kk][b] = dup_f32(g_xn[b * K + k0 + kk]);
    }
    __syncthreads();

    int nc = blockIdx.x * 1024 + threadIdx.x * 4;
    const float* W;
    int Nw, nl;
    if (nc < 4096)      { W = wq; Nw = 4096; nl = nc; }
    else if (nc < 5120) { W = wk; Nw = 1024; nl = nc - 4096; }
    else                { W = wv; Nw = 1024; nl = nc - 5120; }

    unsigned long long a01[8], a23[8];
#pragma unroll
    for (int b = 0; b < 8; ++b) { a01[b] = 0ull; a23[b] = 0ull; }

    const float* wp = W + (size_t)k0 * Nw + nl;
#pragma unroll 8
    for (int kk = 0; kk < KCH; ++kk) GEMM_KSTEP(wp, Nw);

#pragma unroll
    for (int b = 0; b < 8; ++b) {
        ulonglong2 o;
        o.x = a01[b];
        o.y = a23[b];
        *(ulonglong2*)(g_PA + ((size_t)blockIdx.y * 8 + b) * 6144 + nc) = o;
    }
}

// ------------------------- fused w1|w3 GEMM (N=28672), inline norm ----------
__global__ __launch_bounds__(256, 4) void gemm_w13(const float* __restrict__ w1,
                                                   const float* __restrict__ w3,
                                                   const float* __restrict__ gamma) {
    const int KCH = 256;
    __shared__ __align__(16) unsigned long long xs[KCH][8];
    const int K = DM;
    int k0 = blockIdx.y * KCH;
    {
        int bb = threadIdx.x & 7;
        float sq = 0.f;
#pragma unroll
        for (int i = 0; i < 16; ++i) sq += g_bsq[bb * 16 + i];
        float rn = rsqrtf(sq * (1.0f / DM));
        for (int i = threadIdx.x; i < KCH * 8; i += 256) {
            int kk = i >> 3;
            xs[kk][bb] = dup_f32(g_h[bb * K + k0 + kk] * rn * gamma[k0 + kk]);
        }
    }
    __syncthreads();

    int nc = blockIdx.x * 1024 + threadIdx.x * 4;
    const float* W;
    float* P;
    int nl;
    if (nc < HID) { W = w1; P = g_PA; nl = nc; }
    else          { W = w3; P = g_PB; nl = nc - HID; }

    unsigned long long a01[8], a23[8];
#pragma unroll
    for (int b = 0; b < 8; ++b) { a01[b] = 0ull; a23[b] = 0ull; }

    const float* wp = W + (size_t)k0 * HID + nl;
#pragma unroll 8
    for (int kk = 0; kk < KCH; ++kk) GEMM_KSTEP(wp, HID);

#pragma unroll
    for (int b = 0; b < 8; ++b) {
        ulonglong2 o;
        o.x = a01[b];
        o.y = a23[b];
        *(ulonglong2*)(P + ((size_t)blockIdx.y * 8 + b) * HID + nl) = o;
    }
}

// --------------- QKV combine (sum 64 partials) + RoPE, float4 ---------------
__global__ void qkv_finish(const int* __restrict__ sp) {
    int p = blockIdx.x * 256 + threadIdx.x; // 12288 float4 slots
    int b = p / 1536;
    int r = p - b * 1536;
    int c0 = r * 4;
    float4 s = make_float4(0.f, 0.f, 0.f, 0.f);
#pragma unroll 8
    for (int ks = 0; ks < 64; ++ks) {
        float4 v = *(const float4*)(g_PA + ((size_t)ks * 8 + b) * 6144 + c0);
        s.x += v.x; s.y += v.y; s.z += v.z; s.w += v.w;
    }
    int pos = *sp;
    if (c0 < 5120) {
        int cc = (c0 < 4096) ? c0 : c0 - 4096;
        int i0 = (cc & 127) >> 1;
        float if0 = powf(10000.0f, -(float)i0 * (1.0f / 64.0f));
        float if1 = powf(10000.0f, -(float)(i0 + 1) * (1.0f / 64.0f));
        float sn0, cs0, sn1, cs1;
        sincosf((float)pos * if0, &sn0, &cs0);
        sincosf((float)pos * if1, &sn1, &cs1);
        float4 o;
        o.x = s.x * cs0 - s.y * sn0;
        o.y = s.x * sn0 + s.y * cs0;
        o.z = s.z * cs1 - s.w * sn1;
        o.w = s.z * sn1 + s.w * cs1;
        if (c0 < 4096)
            *(float4*)(g_xq + b * 4096 + c0) = o;
        else
            *(float4*)(g_xk + b * 1024 + (c0 - 4096)) = o;
    } else {
        *(float4*)(g_xv + b * 1024 + (c0 - 5120)) = s;
    }
}

// --------------- attention partial, ACH=256, 256 thr, 512 blocks ------------
__global__ __launch_bounds__(256) void attn_part(const float* __restrict__ ck,
                                                 const float* __restrict__ cv,
                                                 const int* __restrict__ sp) {
    int chunk = blockIdx.x, kv = blockIdx.y, b = blockIdx.z;
    int pos = *sp;
    int L = pos + 1;
    int s0 = chunk * ACH;
    int tid = threadIdx.x;
    int w = tid >> 5, l = tid & 31;

    __shared__ float4 qs[4][32];
    __shared__ float4 sc4[ACH];
    __shared__ float Mh[4], Lh[4];
    __shared__ float4 vred[8][4][32];

    if (tid < 128) {
        int h = tid >> 5, q = tid & 31;
        qs[h][q] = *(const float4*)(g_xq + (((b << 5) + (kv << 2) + h) << 7) + q * 4);
    }
    __syncthreads();

    const float scale = 0.08838834764831845f;
    const float4* kbase = (const float4*)(ck + ((size_t)b * MSEQ) * (NKV * HD) + kv * HD);
    const float4* xkrow = (const float4*)(g_xk + (((b << 3) + kv) << 7));

    float4 qv0 = qs[0][l], qv1 = qs[1][l], qv2 = qs[2][l], qv3 = qs[3][l];

#pragma unroll
    for (int i = 0; i < ACH / 32; ++i) {
        int p0 = i * 32 + w;
        float4 k4[4];
#pragma unroll
        for (int j = 0; j < 4; ++j) {
            int s = s0 + p0 + j * 8;
            const float4* kr = (s == pos) ? xkrow : (kbase + (size_t)s * (NKV * HD / 4));
            k4[j] = (s < L) ? kr[l] : make_float4(0.f, 0.f, 0.f, 0.f);
        }
        float d[4][4];
#pragma unroll
        for (int j = 0; j < 4; ++j) {
            d[j][0] = k4[j].x * qv0.x + k4[j].y * qv0.y + k4[j].z * qv0.z + k4[j].w * qv0.w;
            d[j][1] = k4[j].x * qv1.x + k4[j].y * qv1.y + k4[j].z * qv1.z + k4[j].w * qv1.w;
            d[j][2] = k4[j].x * qv2.x + k4[j].y * qv2.y + k4[j].z * qv2.z + k4[j].w * qv2.w;
            d[j][3] = k4[j].x * qv3.x + k4[j].y * qv3.y + k4[j].z * qv3.z + k4[j].w * qv3.w;
        }
#pragma unroll
        for (int o = 16; o; o >>= 1) {
#pragma unroll
            for (int j = 0; j < 4; ++j) {
                d[j][0] += __shfl_xor_sync(0xffffffffu, d[j][0], o);
                d[j][1] += __shfl_xor_sync(0xffffffffu, d[j][1], o);
                d[j][2] += __shfl_xor_sync(0xffffffffu, d[j][2], o);
                d[j][3] += __shfl_xor_sync(0xffffffffu, d[j][3], o);
            }
        }
        if (l == 0) {
#pragma unroll
            for (int j = 0; j < 4; ++j) {
                int s = s0 + p0 + j * 8;
                sc4[p0 + j * 8] = (s < L)
                    ? make_float4(d[j][0] * scale, d[j][1] * scale,
                                  d[j][2] * scale, d[j][3] * scale)
                    : make_float4(-1e30f, -1e30f, -1e30f, -1e30f);
            }
        }
    }
    __syncthreads();

    if (w < 4) {
        const float* scf = (const float*)sc4;
        float v[8];
#pragma unroll
        for (int j = 0; j < 8; ++j) v[j] = scf[(l + 32 * j) * 4 + w];
        float m = v[0];
#pragma unroll
        for (int j = 1; j < 8; ++j) m = fmaxf(m, v[j]);
#pragma unroll
        for (int o = 16; o; o >>= 1) m = fmaxf(m, __shfl_xor_sync(0xffffffffu, m, o));
        float pj[8];
        float sum = 0.f;
#pragma unroll
        for (int j = 0; j < 8; ++j) {
            pj[j] = expf(v[j] - m);
            sum += pj[j];
        }
#pragma unroll
        for (int o = 16; o; o >>= 1) sum += __shfl_xor_sync(0xffffffffu, sum, o);
        float* scw = (float*)sc4;
#pragma unroll
        for (int j = 0; j < 8; ++j) scw[(l + 32 * j) * 4 + w] = pj[j];
        if (!l) { Mh[w] = m; Lh[w] = sum; }
    }
    __syncthreads();

    float4 a0 = make_float4(0.f, 0.f, 0.f, 0.f);
    float4 a1 = a0, a2 = a0, a3 = a0;
    int nc_ = pos - s0;
    if (nc_ > ACH) nc_ = ACH;
    if (nc_ < 0) nc_ = 0;
    const float4* vr = (const float4*)(cv + ((size_t)(b * MSEQ + s0)) * (NKV * HD) + kv * HD) + l;
#pragma unroll 8
    for (int ss = w; ss < nc_; ss += 8) {
        float4 v = vr[(size_t)ss * (NKV * HD / 4)];
        float4 p = sc4[ss];
        fma4(a0, p.x, v);
        fma4(a1, p.y, v);
        fma4(a2, p.z, v);
        fma4(a3, p.w, v);
    }
    int lp = pos - s0;
    if (lp >= 0 && lp < ACH && (lp & 7) == w) {
        float4 v = ((const float4*)(g_xv + (((b << 3) + kv) << 7)))[l];
        float4 p = sc4[lp];
        fma4(a0, p.x, v);
        fma4(a1, p.y, v);
        fma4(a2, p.z, v);
        fma4(a3, p.w, v);
    }
    vred[w][0][l] = a0;
    vred[w][1][l] = a1;
    vred[w][2][l] = a2;
    vred[w][3][l] = a3;
    __syncthreads();

    {
        int h = tid >> 6, j = tid & 63;
        float2 s2 = make_float2(0.f, 0.f);
#pragma unroll
        for (int ww = 0; ww < 8; ++ww) {
            float2 v = ((const float2*)vred[ww][h])[j];
            s2.x += v.x;
            s2.y += v.y;
        }
        int hg = (kv << 2) + h;
        *(float2*)(g_po + ((((size_t)(b << 5) + hg) << 3) + chunk) * HD + j * 2) = s2;
    }
    if (tid < 4) {
        int hg = (kv << 2) + tid;
        g_pm[(((b << 5) + hg) << 3) + chunk] = Mh[tid];
        g_pl[(((b << 5) + hg) << 3) + chunk] = Lh[tid];
    }
}

// --------- combine partials + residual; stash per-colblock sumsq (WIDE) -----
__global__ void finish_res(int KS) {
    __shared__ float red[8];
    int b = blockIdx.y;
    int c = blockIdx.x * 256 + threadIdx.x; // grid.x = 16 -> 4096 cols
    float s = g_h[b * DM + c];
#pragma unroll 8
    for (int ks = 0; ks < KS; ++ks) s += g_PA[((size_t)ks * 8 + b) * DM + c];
    g_h[b * DM + c] = s;
    float sq = s * s;
    int lane = threadIdx.x & 31, wid = threadIdx.x >> 5;
#pragma unroll
    for (int o = 16; o; o >>= 1) sq += __shfl_xor_sync(0xffffffffu, sq, o);
    if (!lane) red[wid] = sq;
    __syncthreads();
    if (threadIdx.x == 0) {
        float t = 0.f;
#pragma unroll
        for (int ww = 0; ww < 8; ++ww) t += red[ww];
        g_bsq[b * 16 + blockIdx.x] = t;
    }
}

// --------------- ffn gate: g = silu(x@w1) * (x@w3), float4 -------------------
__global__ void ffn_act(int KS) {
    int b = blockIdx.y;
    int c = (blockIdx.x * 256 + threadIdx.x) * 4;
    float4 s1 = make_float4(0.f, 0.f, 0.f, 0.f), s3 = s1;
#pragma unroll 8
    for (int ks = 0; ks < KS; ++ks) {
        float4 v1 = *(const float4*)(g_PA + ((size_t)ks * 8 + b) * HID + c);
        float4 v3 = *(const float4*)(g_PB + ((size_t)ks * 8 + b) * HID + c);
        s1.x += v1.x; s1.y += v1.y; s1.z += v1.z; s1.w += v1.w;
        s3.x += v3.x; s3.y += v3.y; s3.z += v3.z; s3.w += v3.w;
    }
    float4 o;
    o.x = s1.x / (1.0f + expf(-s1.x)) * s3.x;
    o.y = s1.y / (1.0f + expf(-s1.y)) * s3.y;
    o.z = s1.z / (1.0f + expf(-s1.z)) * s3.z;
    o.w = s1.w / (1.0f + expf(-s1.w)) * s3.w;
    *(float4*)(g_g + b * HID + c) = o;
}

// --------------- logits combine, float4 --------------------------------------
__global__ void wout_finish(float* __restrict__ out, int KS) {
    int b = blockIdx.y;
    int c4 = blockIdx.x * 256 + threadIdx.x;
    if (c4 >= VOC / 4) return;
    int c = c4 * 4;
    float4 s = make_float4(0.f, 0.f, 0.f, 0.f);
#pragma unroll 4
    for (int ks = 0; ks < KS; ++ks) {
        float4 v = *(const float4*)(g_PA + ((size_t)ks * 8 + b) * VOC + c);
        s.x += v.x; s.y += v.y; s.z += v.z; s.w += v.w;
    }
    *(float4*)(out + b * VOC + c) = s;
}

// ------------------------- launch --------------------------------------------
extern "C" void kernel_launch(void* const* d_in, const int* in_sizes, int n_in,
                              void* d_out, int out_size) {
    const int* tokens = (const int*)d_in[0];
    const int* sp = (const int*)d_in[1];
    const float* emb = (const float*)d_in[2];
    const float* g1 = (const float*)d_in[3];
    const float* g2 = (const float*)d_in[4];
    const float* gf = (const float*)d_in[5];
    const float* wq = (const float*)d_in[6];
    const float* wk = (const float*)d_in[7];
    const float* wv = (const float*)d_in[8];
    const float* wo = (const float*)d_in[9];
    const float* w1 = (const float*)d_in[10];
    const float* w2 = (const float*)d_in[11];
    const float* w3 = (const float*)d_in[12];
    const float* wout = (const float*)d_in[13];
    const float* ck = (const float*)d_in[14];
    const float* cv = (const float*)d_in[15];
    float* out = (float*)d_out;

    embed_norm<<<8, 256>>>(tokens, emb, g1);
    // QKV: KS=64, kchunk=64 -> 384 blocks
    gemm_qkv<<<dim3(6, 64), 256>>>(wq, wk, wv);
    qkv_finish<<<48, 256>>>(sp);
    // attention: 8 chunks x 8 kv x 8 batch = 512 blocks (single wave)
    attn_part<<<dim3(NCHK, 8, 8), 256>>>(ck, cv, sp);
    // wo: KS=128, kchunk=32 -> 512 blocks; X = fused attn chunk-combine
    gemm8<1, 0, 32><<<dim3(4, 128), 256>>>(wo, nullptr, 4096, 4096);
    finish_res<<<dim3(16, 8), 256>>>(128);
    // w1|w3 fused, rmsnorm(gamma2) inline: KS=16, kchunk=256 -> 448 blocks
    gemm_w13<<<dim3(28, 16), 256>>>(w1, w3, g2);
    ffn_act<<<dim3(14, 8), 256>>>(16);
    // w2: KS=128, kchunk=112 -> 512 blocks
    gemm8<2, 0, 112><<<dim3(4, 128), 256>>>(w2, nullptr, 14336, 4096);
    finish_res<<<dim3(16, 8), 256>>>(128);
    // w_out, rmsnorm(gamma_f) inline: KS=16, kchunk=256 -> 512 blocks
    gemm8<3, 0, 256><<<dim3(32, 16), 256>>>(wout, gf, 4096, 32000);
    wout_finish<<<dim3(32, 8), 256>>>(out, 16);
}

// round 15
// speedup vs baseline: 1.2999x; 1.2999x over previous
#include <cuda_runtime.h>
#include <cuda_bf16.h>
#include <math.h>

// ---------------------------------------------------------------------------
// Llama-style decode step, BATCH=8, S=1. R13 CHAMPION (verified 313.9us):
// GEMVs: f32x2 FMA, 4 cols/thread, 256 thr, (256,4) bounds, unroll-8,
// coalesced per-b X staging, .cs weights only (partials L2-default).
// Split-K: qkv 64, wo 128, w13 16, w2 128, wout 16 (all ~3-3.5 blk/SM).
// Attention: ACH=256 single wave, ILP-4 score pass, separate combine.
// ---------------------------------------------------------------------------

#define DM 4096
#define NH 32
#define NKV 8
#define HD 128
#define HID 14336
#define VOC 32000
#define MSEQ 2048
#define B8 8
#define ACH 256   // attention chunk length
#define NCHK 8    // MSEQ / ACH

// ------------------------- scratch (device globals) -------------------------
__device__ float g_h[B8 * DM];
__device__ float g_xn[B8 * DM];
__device__ float g_xq[B8 * NH * HD];
__device__ float g_xk[B8 * NKV * HD];
__device__ float g_xv[B8 * NKV * HD];
__device__ float g_pm[B8 * NH * NCHK];
__device__ float g_pl[B8 * NH * NCHK];
__device__ float g_po[B8 * NH * NCHK * HD];
__device__ float g_attn[B8 * DM];
__device__ float g_g[B8 * HID];
__device__ float g_bsq[B8 * 16];
__device__ float g_PA[16 * 8 * 32000];
__device__ float g_PB[16 * 8 * 14336];

// ------------------------- helpers -------------------------
__device__ __forceinline__ void fma4(float4& a, float s, const float4& w) {
    a.x = fmaf(s, w.x, a.x);
    a.y = fmaf(s, w.y, a.y);
    a.z = fmaf(s, w.z, a.z);
    a.w = fmaf(s, w.w, a.w);
}

__device__ __forceinline__ unsigned long long dup_f32(float v) {
    unsigned long long pv;
    asm("mov.b64 %0, {%1, %1};" : "=l"(pv) : "f"(v));
    return pv;
}

// -------- GEMM inner macro: 1 LDG.128(.cs) + 4 LDS.128 + 16 FFMA2 per k -----
#define GEMM_KSTEP(wp, stride)                                                 \
    {                                                                          \
        ulonglong2 w2;                                                         \
        asm("ld.global.cs.v2.u64 {%0,%1}, [%2];"                               \
            : "=l"(w2.x), "=l"(w2.y) : "l"(wp));                               \
        (wp) += (stride);                                                      \
        _Pragma("unroll") for (int p = 0; p < 4; ++p) {                        \
            ulonglong2 xp = *(const ulonglong2*)&xs[kk][2 * p];                \
            asm("fma.rn.f32x2 %0, %4, %6, %0;\n\t"                             \
                "fma.rn.f32x2 %1, %4, %7, %1;\n\t"                             \
                "fma.rn.f32x2 %2, %5, %6, %2;\n\t"                             \
                "fma.rn.f32x2 %3, %5, %7, %3;"                                 \
                : "+l"(a01[2 * p]), "+l"(a23[2 * p]),                          \
                  "+l"(a01[2 * p + 1]), "+l"(a23[2 * p + 1])                   \
                : "l"(xp.x), "l"(xp.y), "l"(w2.x), "l"(w2.y));                 \
        }                                                                      \
    }

// ------------------------- kernel 0: embed + rmsnorm(gamma1) ----------------
__global__ void embed_norm(const int* __restrict__ tokens,
                           const float* __restrict__ emb,
                           const float* __restrict__ gamma) {
    __shared__ float red[8];
    int b = blockIdx.x;
    int tok = tokens[b];
    const float* row = emb + (size_t)tok * DM;
    float loc[16];
    float sq = 0.f;
#pragma unroll
    for (int i = 0; i < 16; ++i) {
        float v = row[threadIdx.x + i * 256];
        loc[i] = v;
        sq += v * v;
    }
    int lane = threadIdx.x & 31, wid = threadIdx.x >> 5;
#pragma unroll
    for (int o = 16; o; o >>= 1) sq += __shfl_xor_sync(0xffffffffu, sq, o);
    if (!lane) red[wid] = sq;
    __syncthreads();
    float tot = 0.f;
#pragma unroll
    for (int w = 0; w < 8; ++w) tot += red[w];
    float rn = rsqrtf(tot * (1.0f / DM));
#pragma unroll
    for (int i = 0; i < 16; ++i) {
        int c = threadIdx.x + i * 256;
        g_h[b * DM + c] = loc[i];
        g_xn[b * DM + c] = loc[i] * rn * gamma[c];
    }
}

// ------------------------- generic split-K GEMM (M=8), f32x2 ----------------
// XSEL: 0 = g_xn, 1 = g_attn, 2 = g_g.  PSEL: 0 = g_PA, 1 = g_PB.
template <int XSEL, int PSEL, int KCH>
__global__ __launch_bounds__(256, 4) void gemm8(const float* __restrict__ W,
                                                int K, int N) {
    const float* X = (XSEL == 0) ? g_xn : (XSEL == 1) ? g_attn : g_g;
    float* P = (PSEL == 0) ? g_PA : g_PB;

    __shared__ __align__(16) unsigned long long xs[KCH][8];

    int k0 = blockIdx.y * KCH;
#pragma unroll
    for (int b = 0; b < 8; ++b)
        for (int kk = threadIdx.x; kk < KCH; kk += 256)
            xs[kk][b] = dup_f32(X[b * K + k0 + kk]);
    __syncthreads();

    int n0 = blockIdx.x * 1024 + threadIdx.x * 4;
    if (n0 >= N) return;

    unsigned long long a01[8], a23[8];
#pragma unroll
    for (int b = 0; b < 8; ++b) { a01[b] = 0ull; a23[b] = 0ull; }

    const float* wp = W + (size_t)k0 * N + n0;
#pragma unroll 8
    for (int kk = 0; kk < KCH; ++kk) GEMM_KSTEP(wp, N);

#pragma unroll
    for (int b = 0; b < 8; ++b) {
        ulonglong2 o;
        o.x = a01[b];
        o.y = a23[b];
        *(ulonglong2*)(P + ((size_t)blockIdx.y * 8 + b) * N + n0) = o;
    }
}

// ------------------------- fused QKV GEMM (concat N=6144) -------------------
__global__ __launch_bounds__(256, 4) void gemm_qkv(const float* __restrict__ wq,
                                                   const float* __restrict__ wk,
                                                   const float* __restrict__ wv) {
    const int KCH = 64;   // KS=64 -> 384 blocks
    __shared__ __align__(16) unsigned long long xs[KCH][8];
    const int K = DM;
    int k0 = blockIdx.y * KCH;
#pragma unroll
    for (int b = 0; b < 8; ++b)
        for (int kk = threadIdx.x; kk < KCH; kk += 256)
            xs[kk][b] = dup_f32(g_xn[b * K + k0 + kk]);
    __syncthreads();

    int nc = blockIdx.x * 1024 + threadIdx.x * 4;
    const float* W;
    int Nw, nl;
    if (nc < 4096)      { W = wq; Nw = 4096; nl = nc; }
    else if (nc < 5120) { W = wk; Nw = 1024; nl = nc - 4096; }
    else                { W = wv; Nw = 1024; nl = nc - 5120; }

    unsigned long long a01[8], a23[8];
#pragma unroll
    for (int b = 0; b < 8; ++b) { a01[b] = 0ull; a23[b] = 0ull; }

    const float* wp = W + (size_t)k0 * Nw + nl;
#pragma unroll 8
    for (int kk = 0; kk < KCH; ++kk) GEMM_KSTEP(wp, Nw);

#pragma unroll
    for (int b = 0; b < 8; ++b) {
        ulonglong2 o;
        o.x = a01[b];
        o.y = a23[b];
        *(ulonglong2*)(g_PA + ((size_t)blockIdx.y * 8 + b) * 6144 + nc) = o;
    }
}

// ------------------------- fused w1|w3 GEMM (N=28672) -----------------------
__global__ __launch_bounds__(256, 4) void gemm_w13(const float* __restrict__ w1,
                                                   const float* __restrict__ w3) {
    const int KCH = 256;
    __shared__ __align__(16) unsigned long long xs[KCH][8];
    const int K = DM;
    int k0 = blockIdx.y * KCH;
#pragma unroll
    for (int b = 0; b < 8; ++b)
        for (int kk = threadIdx.x; kk < KCH; kk += 256)
            xs[kk][b] = dup_f32(g_xn[b * K + k0 + kk]);
    __syncthreads();

    int nc = blockIdx.x * 1024 + threadIdx.x * 4;
    const float* W;
    float* P;
    int nl;
    if (nc < HID) { W = w1; P = g_PA; nl = nc; }
    else          { W = w3; P = g_PB; nl = nc - HID; }

    unsigned long long a01[8], a23[8];
#pragma unroll
    for (int b = 0; b < 8; ++b) { a01[b] = 0ull; a23[b] = 0ull; }

    const float* wp = W + (size_t)k0 * HID + nl;
#pragma unroll 8
    for (int kk = 0; kk < KCH; ++kk) GEMM_KSTEP(wp, HID);

#pragma unroll
    for (int b = 0; b < 8; ++b) {
        ulonglong2 o;
        o.x = a01[b];
        o.y = a23[b];
        *(ulonglong2*)(P + ((size_t)blockIdx.y * 8 + b) * HID + nl) = o;
    }
}

// --------------- QKV combine (sum 64 partials) + RoPE, float4 ---------------
__global__ void qkv_finish(const int* __restrict__ sp) {
    int p = blockIdx.x * 256 + threadIdx.x; // 12288 float4 slots
    int b = p / 1536;
    int r = p - b * 1536;
    int c0 = r * 4;
    float4 s = make_float4(0.f, 0.f, 0.f, 0.f);
#pragma unroll 8
    for (int ks = 0; ks < 64; ++ks) {
        float4 v = *(const float4*)(g_PA + ((size_t)ks * 8 + b) * 6144 + c0);
        s.x += v.x; s.y += v.y; s.z += v.z; s.w += v.w;
    }
    int pos = *sp;
    if (c0 < 5120) {
        int cc = (c0 < 4096) ? c0 : c0 - 4096;
        int i0 = (cc & 127) >> 1;
        float if0 = powf(10000.0f, -(float)i0 * (1.0f / 64.0f));
        float if1 = powf(10000.0f, -(float)(i0 + 1) * (1.0f / 64.0f));
        float sn0, cs0, sn1, cs1;
        sincosf((float)pos * if0, &sn0, &cs0);
        sincosf((float)pos * if1, &sn1, &cs1);
        float4 o;
        o.x = s.x * cs0 - s.y * sn0;
        o.y = s.x * sn0 + s.y * cs0;
        o.z = s.z * cs1 - s.w * sn1;
        o.w = s.z * sn1 + s.w * cs1;
        if (c0 < 4096)
            *(float4*)(g_xq + b * 4096 + c0) = o;
        else
            *(float4*)(g_xk + b * 1024 + (c0 - 4096)) = o;
    } else {
        *(float4*)(g_xv + b * 1024 + (c0 - 5120)) = s;
    }
}

// --------------- attention partial, ACH=256, 256 thr, 512 blocks ------------
__global__ __launch_bounds__(256) void attn_part(const float* __restrict__ ck,
                                                 const float* __restrict__ cv,
                                                 const int* __restrict__ sp) {
    int chunk = blockIdx.x, kv = blockIdx.y, b = blockIdx.z;
    int pos = *sp;
    int L = pos + 1;
    int s0 = chunk * ACH;
    int tid = threadIdx.x;
    int w = tid >> 5, l = tid & 31;

    __shared__ float4 qs[4][32];
    __shared__ float4 sc4[ACH];
    __shared__ float Mh[4], Lh[4];
    __shared__ float4 vred[8][4][32];

    if (tid < 128) {
        int h = tid >> 5, q = tid & 31;
        qs[h][q] = *(const float4*)(g_xq + (((b << 5) + (kv << 2) + h) << 7) + q * 4);
    }
    __syncthreads();

    const float scale = 0.08838834764831845f;
    const float4* kbase = (const float4*)(ck + ((size_t)b * MSEQ) * (NKV * HD) + kv * HD);
    const float4* xkrow = (const float4*)(g_xk + (((b << 3) + kv) << 7));

    float4 qv0 = qs[0][l], qv1 = qs[1][l], qv2 = qs[2][l], qv3 = qs[3][l];

#pragma unroll
    for (int i = 0; i < ACH / 32; ++i) {
        int p0 = i * 32 + w;
        float4 k4[4];
#pragma unroll
        for (int j = 0; j < 4; ++j) {
            int s = s0 + p0 + j * 8;
            const float4* kr = (s == pos) ? xkrow : (kbase + (size_t)s * (NKV * HD / 4));
            k4[j] = (s < L) ? kr[l] : make_float4(0.f, 0.f, 0.f, 0.f);
        }
        float d[4][4];
#pragma unroll
        for (int j = 0; j < 4; ++j) {
            d[j][0] = k4[j].x * qv0.x + k4[j].y * qv0.y + k4[j].z * qv0.z + k4[j].w * qv0.w;
            d[j][1] = k4[j].x * qv1.x + k4[j].y * qv1.y + k4[j].z * qv1.z + k4[j].w * qv1.w;
            d[j][2] = k4[j].x * qv2.x + k4[j].y * qv2.y + k4[j].z * qv2.z + k4[j].w * qv2.w;
            d[j][3] = k4[j].x * qv3.x + k4[j].y * qv3.y + k4[j].z * qv3.z + k4[j].w * qv3.w;
        }
#pragma unroll
        for (int o = 16; o; o >>= 1) {
#pragma unroll
            for (int j = 0; j < 4; ++j) {
                d[j][0] += __shfl_xor_sync(0xffffffffu, d[j][0], o);
                d[j][1] += __shfl_xor_sync(0xffffffffu, d[j][1], o);
                d[j][2] += __shfl_xor_sync(0xffffffffu, d[j][2], o);
                d[j][3] += __shfl_xor_sync(0xffffffffu, d[j][3], o);
            }
        }
        if (l == 0) {
#pragma unroll
            for (int j = 0; j < 4; ++j) {
                int s = s0 + p0 + j * 8;
                sc4[p0 + j * 8] = (s < L)
                    ? make_float4(d[j][0] * scale, d[j][1] * scale,
                                  d[j][2] * scale, d[j][3] * scale)
                    : make_float4(-1e30f, -1e30f, -1e30f, -1e30f);
            }
        }
    }
    __syncthreads();

    if (w < 4) {
        const float* scf = (const float*)sc4;
        float v[8];
#pragma unroll
        for (int j = 0; j < 8; ++j) v[j] = scf[(l + 32 * j) * 4 + w];
        float m = v[0];
#pragma unroll
        for (int j = 1; j < 8; ++j) m = fmaxf(m, v[j]);
#pragma unroll
        for (int o = 16; o; o >>= 1) m = fmaxf(m, __shfl_xor_sync(0xffffffffu, m, o));
        float pj[8];
        float sum = 0.f;
#pragma unroll
        for (int j = 0; j < 8; ++j) {
            pj[j] = expf(v[j] - m);
            sum += pj[j];
        }
#pragma unroll
        for (int o = 16; o; o >>= 1) sum += __shfl_xor_sync(0xffffffffu, sum, o);
        float* scw = (float*)sc4;
#pragma unroll
        for (int j = 0; j < 8; ++j) scw[(l + 32 * j) * 4 + w] = pj[j];
        if (!l) { Mh[w] = m; Lh[w] = sum; }
    }
    __syncthreads();

    float4 a0 = make_float4(0.f, 0.f, 0.f, 0.f);
    float4 a1 = a0, a2 = a0, a3 = a0;
    int nc_ = pos - s0;
    if (nc_ > ACH) nc_ = ACH;
    if (nc_ < 0) nc_ = 0;
    const float4* vr = (const float4*)(cv + ((size_t)(b * MSEQ + s0)) * (NKV * HD) + kv * HD) + l;
#pragma unroll 8
    for (int ss = w; ss < nc_; ss += 8) {
        float4 v = vr[(size_t)ss * (NKV * HD / 4)];
        float4 p = sc4[ss];
        fma4(a0, p.x, v);
        fma4(a1, p.y, v);
        fma4(a2, p.z, v);
        fma4(a3, p.w, v);
    }
    int lp = pos - s0;
    if (lp >= 0 && lp < ACH && (lp & 7) == w) {
        float4 v = ((const float4*)(g_xv + (((b << 3) + kv) << 7)))[l];
        float4 p = sc4[lp];
        fma4(a0, p.x, v);
        fma4(a1, p.y, v);
        fma4(a2, p.z, v);
        fma4(a3, p.w, v);
    }
    vred[w][0][l] = a0;
    vred[w][1][l] = a1;
    vred[w][2][l] = a2;
    vred[w][3][l] = a3;
    __syncthreads();

    {
        int h = tid >> 6, j = tid & 63;
        float2 s2 = make_float2(0.f, 0.f);
#pragma unroll
        for (int ww = 0; ww < 8; ++ww) {
            float2 v = ((const float2*)vred[ww][h])[j];
            s2.x += v.x;
            s2.y += v.y;
        }
        int hg = (kv << 2) + h;
        *(float2*)(g_po + ((((size_t)(b << 5) + hg) << 3) + chunk) * HD + j * 2) = s2;
    }
    if (tid < 4) {
        int hg = (kv << 2) + tid;
        g_pm[(((b << 5) + hg) << 3) + chunk] = Mh[tid];
        g_pl[(((b << 5) + hg) << 3) + chunk] = Lh[tid];
    }
}

// --------------- attention: combine chunk partials ---------------------------
__global__ void attn_combine() {
    int h = blockIdx.x, b = blockIdx.y, d = threadIdx.x; // 128 threads
    int base = ((b << 5) + h) << 3;
    float M = -1e30f;
#pragma unroll
    for (int c = 0; c < NCHK; ++c) M = fmaxf(M, g_pm[base + c]);
    float Ls = 0.f, o = 0.f;
#pragma unroll
    for (int c = 0; c < NCHK; ++c) {
        float w = expf(g_pm[base + c] - M);
        Ls += g_pl[base + c] * w;
        o += g_po[(size_t)(base + c) * HD + d] * w;
    }
    g_attn[((b << 5) + h) * HD + d] = o / Ls;
}

// --------- combine partials + residual; stash per-colblock sumsq (WIDE) -----
__global__ void finish_res(int KS) {
    __shared__ float red[8];
    int b = blockIdx.y;
    int c = blockIdx.x * 256 + threadIdx.x; // grid.x = 16 -> 4096 cols
    float s = g_h[b * DM + c];
#pragma unroll 8
    for (int ks = 0; ks < KS; ++ks) s += g_PA[((size_t)ks * 8 + b) * DM + c];
    g_h[b * DM + c] = s;
    float sq = s * s;
    int lane = threadIdx.x & 31, wid = threadIdx.x >> 5;
#pragma unroll
    for (int o = 16; o; o >>= 1) sq += __shfl_xor_sync(0xffffffffu, sq, o);
    if (!lane) red[wid] = sq;
    __syncthreads();
    if (threadIdx.x == 0) {
        float t = 0.f;
#pragma unroll
        for (int ww = 0; ww < 8; ++ww) t += red[ww];
        g_bsq[b * 16 + blockIdx.x] = t;
    }
}

// --------------- rmsnorm using stashed sums (WIDE) --------------------------
__global__ void finish_norm(const float* __restrict__ gamma) {
    int b = blockIdx.y;
    int c = blockIdx.x * 256 + threadIdx.x;
    float sq = 0.f;
#pragma unroll
    for (int i = 0; i < 16; ++i) sq += g_bsq[b * 16 + i];
    float rn = rsqrtf(sq * (1.0f / DM));
    g_xn[b * DM + c] = g_h[b * DM + c] * rn * gamma[c];
}

// --------------- ffn gate: g = silu(x@w1) * (x@w3), float4 -------------------
__global__ void ffn_act(int KS) {
    int b = blockIdx.y;
    int c = (blockIdx.x * 256 + threadIdx.x) * 4;
    float4 s1 = make_float4(0.f, 0.f, 0.f, 0.f), s3 = s1;
#pragma unroll 8
    for (int ks = 0; ks < KS; ++ks) {
        float4 v1 = *(const float4*)(g_PA + ((size_t)ks * 8 + b) * HID + c);
        float4 v3 = *(const float4*)(g_PB + ((size_t)ks * 8 + b) * HID + c);
        s1.x += v1.x; s1.y += v1.y; s1.z += v1.z; s1.w += v1.w;
        s3.x += v3.x; s3.y += v3.y; s3.z += v3.z; s3.w += v3.w;
    }
    float4 o;
    o.x = s1.x / (1.0f + expf(-s1.x)) * s3.x;
    o.y = s1.y / (1.0f + expf(-s1.y)) * s3.y;
    o.z = s1.z / (1.0f + expf(-s1.z)) * s3.z;
    o.w = s1.w / (1.0f + expf(-s1.w)) * s3.w;
    *(float4*)(g_g + b * HID + c) = o;
}

// --------------- logits combine, float4 --------------------------------------
__global__ void wout_finish(float* __restrict__ out, int KS) {
    int b = blockIdx.y;
    int c4 = blockIdx.x * 256 + threadIdx.x;
    if (c4 >= VOC / 4) return;
    int c = c4 * 4;
    float4 s = make_float4(0.f, 0.f, 0.f, 0.f);
#pragma unroll 4
    for (int ks = 0; ks < KS; ++ks) {
        float4 v = *(const float4*)(g_PA + ((size_t)ks * 8 + b) * VOC + c);
        s.x += v.x; s.y += v.y; s.z += v.z; s.w += v.w;
    }
    *(float4*)(out + b * VOC + c) = s;
}

// ------------------------- launch --------------------------------------------
extern "C" void kernel_launch(void* const* d_in, const int* in_sizes, int n_in,
                              void* d_out, int out_size) {
    const int* tokens = (const int*)d_in[0];
    const int* sp = (const int*)d_in[1];
    const float* emb = (const float*)d_in[2];
    const float* g1 = (const float*)d_in[3];
    const float* g2 = (const float*)d_in[4];
    const float* gf = (const float*)d_in[5];
    const float* wq = (const float*)d_in[6];
    const float* wk = (const float*)d_in[7];
    const float* wv = (const float*)d_in[8];
    const float* wo = (const float*)d_in[9];
    const float* w1 = (const float*)d_in[10];
    const float* w2 = (const float*)d_in[11];
    const float* w3 = (const float*)d_in[12];
    const float* wout = (const float*)d_in[13];
    const float* ck = (const float*)d_in[14];
    const float* cv = (const float*)d_in[15];
    float* out = (float*)d_out;

    embed_norm<<<8, 256>>>(tokens, emb, g1);
    // QKV: KS=64, kchunk=64 -> 384 blocks
    gemm_qkv<<<dim3(6, 64), 256>>>(wq, wk, wv);
    qkv_finish<<<48, 256>>>(sp);
    // attention: 8 chunks x 8 kv x 8 batch = 512 blocks (single wave)
    attn_part<<<dim3(NCHK, 8, 8), 256>>>(ck, cv, sp);
    attn_combine<<<dim3(32, 8), 128>>>();
    // wo: KS=128, kchunk=32 -> 512 blocks (3.46/SM)
    gemm8<1, 0, 32><<<dim3(4, 128), 256>>>(wo, 4096, 4096);
    finish_res<<<dim3(16, 8), 256>>>(128);
    finish_norm<<<dim3(16, 8), 256>>>(g2);
    // w1|w3 fused: KS=16, kchunk=256 -> 448 blocks
    gemm_w13<<<dim3(28, 16), 256>>>(w1, w3);
    ffn_act<<<dim3(14, 8), 256>>>(16);
    // w2: KS=128, kchunk=112 -> 512 blocks (3.46/SM)
    gemm8<2, 0, 112><<<dim3(4, 128), 256>>>(w2, 14336, 4096);
    finish_res<<<dim3(16, 8), 256>>>(128);
    finish_norm<<<dim3(16, 8), 256>>>(gf);
    // w_out: KS=16, kchunk=256 -> 512 blocks
    gemm8<0, 0, 256><<<dim3(32, 16), 256>>>(wout, 4096, 32000);
    wout_finish<<<dim3(32, 8), 256>>>(out, 16);
}

// round 16
// speedup vs baseline: 1.3124x; 1.0096x over previous
#include <cuda_runtime.h>
#include <cuda_bf16.h>
#include <math.h>

// ---------------------------------------------------------------------------
// Llama-style decode step, BATCH=8, S=1. R13 champion + R16: wide scalar
// qkv_finish (192 blocks) and ffn_act (448 blocks) combine kernels.
// GEMVs: f32x2 FMA, 4 cols/thread, 256 thr, (256,4) bounds, unroll-8,
// coalesced per-b X staging, .cs weights only (partials L2-default).
// Attention: ACH=256 single wave, ILP-4 score pass, separate combine.
// ---------------------------------------------------------------------------

#define DM 4096
#define NH 32
#define NKV 8
#define HD 128
#define HID 14336
#define VOC 32000
#define MSEQ 2048
#define B8 8
#define ACH 256   // attention chunk length
#define NCHK 8    // MSEQ / ACH

// ------------------------- scratch (device globals) -------------------------
__device__ float g_h[B8 * DM];
__device__ float g_xn[B8 * DM];
__device__ float g_xq[B8 * NH * HD];
__device__ float g_xk[B8 * NKV * HD];
__device__ float g_xv[B8 * NKV * HD];
__device__ float g_pm[B8 * NH * NCHK];
__device__ float g_pl[B8 * NH * NCHK];
__device__ float g_po[B8 * NH * NCHK * HD];
__device__ float g_attn[B8 * DM];
__device__ float g_g[B8 * HID];
__device__ float g_bsq[B8 * 16];
__device__ float g_PA[16 * 8 * 32000];
__device__ float g_PB[16 * 8 * 14336];

// ------------------------- helpers -------------------------
__device__ __forceinline__ void fma4(float4& a, float s, const float4& w) {
    a.x = fmaf(s, w.x, a.x);
    a.y = fmaf(s, w.y, a.y);
    a.z = fmaf(s, w.z, a.z);
    a.w = fmaf(s, w.w, a.w);
}

__device__ __forceinline__ unsigned long long dup_f32(float v) {
    unsigned long long pv;
    asm("mov.b64 %0, {%1, %1};" : "=l"(pv) : "f"(v));
    return pv;
}

// -------- GEMM inner macro: 1 LDG.128(.cs) + 4 LDS.128 + 16 FFMA2 per k -----
#define GEMM_KSTEP(wp, stride)                                                 \
    {                                                                          \
        ulonglong2 w2;                                                         \
        asm("ld.global.cs.v2.u64 {%0,%1}, [%2];"                               \
            : "=l"(w2.x), "=l"(w2.y) : "l"(wp));                               \
        (wp) += (stride);                                                      \
        _Pragma("unroll") for (int p = 0; p < 4; ++p) {                        \
            ulonglong2 xp = *(const ulonglong2*)&xs[kk][2 * p];                \
            asm("fma.rn.f32x2 %0, %4, %6, %0;\n\t"                             \
                "fma.rn.f32x2 %1, %4, %7, %1;\n\t"                             \
                "fma.rn.f32x2 %2, %5, %6, %2;\n\t"                             \
                "fma.rn.f32x2 %3, %5, %7, %3;"                                 \
                : "+l"(a01[2 * p]), "+l"(a23[2 * p]),                          \
                  "+l"(a01[2 * p + 1]), "+l"(a23[2 * p + 1])                   \
                : "l"(xp.x), "l"(xp.y), "l"(w2.x), "l"(w2.y));                 \
        }                                                                      \
    }

// ------------------------- kernel 0: embed + rmsnorm(gamma1) ----------------
__global__ void embed_norm(const int* __restrict__ tokens,
                           const float* __restrict__ emb,
                           const float* __restrict__ gamma) {
    __shared__ float red[8];
    int b = blockIdx.x;
    int tok = tokens[b];
    const float* row = emb + (size_t)tok * DM;
    float loc[16];
    float sq = 0.f;
#pragma unroll
    for (int i = 0; i < 16; ++i) {
        float v = row[threadIdx.x + i * 256];
        loc[i] = v;
        sq += v * v;
    }
    int lane = threadIdx.x & 31, wid = threadIdx.x >> 5;
#pragma unroll
    for (int o = 16; o; o >>= 1) sq += __shfl_xor_sync(0xffffffffu, sq, o);
    if (!lane) red[wid] = sq;
    __syncthreads();
    float tot = 0.f;
#pragma unroll
    for (int w = 0; w < 8; ++w) tot += red[w];
    float rn = rsqrtf(tot * (1.0f / DM));
#pragma unroll
    for (int i = 0; i < 16; ++i) {
        int c = threadIdx.x + i * 256;
        g_h[b * DM + c] = loc[i];
        g_xn[b * DM + c] = loc[i] * rn * gamma[c];
    }
}

// ------------------------- generic split-K GEMM (M=8), f32x2 ----------------
// XSEL: 0 = g_xn, 1 = g_attn, 2 = g_g.  PSEL: 0 = g_PA, 1 = g_PB.
template <int XSEL, int PSEL, int KCH>
__global__ __launch_bounds__(256, 4) void gemm8(const float* __restrict__ W,
                                                int K, int N) {
    const float* X = (XSEL == 0) ? g_xn : (XSEL == 1) ? g_attn : g_g;
    float* P = (PSEL == 0) ? g_PA : g_PB;

    __shared__ __align__(16) unsigned long long xs[KCH][8];

    int k0 = blockIdx.y * KCH;
#pragma unroll
    for (int b = 0; b < 8; ++b)
        for (int kk = threadIdx.x; kk < KCH; kk += 256)
            xs[kk][b] = dup_f32(X[b * K + k0 + kk]);
    __syncthreads();

    int n0 = blockIdx.x * 1024 + threadIdx.x * 4;
    if (n0 >= N) return;

    unsigned long long a01[8], a23[8];
#pragma unroll
    for (int b = 0; b < 8; ++b) { a01[b] = 0ull; a23[b] = 0ull; }

    const float* wp = W + (size_t)k0 * N + n0;
#pragma unroll 8
    for (int kk = 0; kk < KCH; ++kk) GEMM_KSTEP(wp, N);

#pragma unroll
    for (int b = 0; b < 8; ++b) {
        ulonglong2 o;
        o.x = a01[b];
        o.y = a23[b];
        *(ulonglong2*)(P + ((size_t)blockIdx.y * 8 + b) * N + n0) = o;
    }
}

// ------------------------- fused QKV GEMM (concat N=6144) -------------------
__global__ __launch_bounds__(256, 4) void gemm_qkv(const float* __restrict__ wq,
                                                   const float* __restrict__ wk,
                                                   const float* __restrict__ wv) {
    const int KCH = 64;   // KS=64 -> 384 blocks
    __shared__ __align__(16) unsigned long long xs[KCH][8];
    const int K = DM;
    int k0 = blockIdx.y * KCH;
#pragma unroll
    for (int b = 0; b < 8; ++b)
        for (int kk = threadIdx.x; kk < KCH; kk += 256)
            xs[kk][b] = dup_f32(g_xn[b * K + k0 + kk]);
    __syncthreads();

    int nc = blockIdx.x * 1024 + threadIdx.x * 4;
    const float* W;
    int Nw, nl;
    if (nc < 4096)      { W = wq; Nw = 4096; nl = nc; }
    else if (nc < 5120) { W = wk; Nw = 1024; nl = nc - 4096; }
    else                { W = wv; Nw = 1024; nl = nc - 5120; }

    unsigned long long a01[8], a23[8];
#pragma unroll
    for (int b = 0; b < 8; ++b) { a01[b] = 0ull; a23[b] = 0ull; }

    const float* wp = W + (size_t)k0 * Nw + nl;
#pragma unroll 8
    for (int kk = 0; kk < KCH; ++kk) GEMM_KSTEP(wp, Nw);

#pragma unroll
    for (int b = 0; b < 8; ++b) {
        ulonglong2 o;
        o.x = a01[b];
        o.y = a23[b];
        *(ulonglong2*)(g_PA + ((size_t)blockIdx.y * 8 + b) * 6144 + nc) = o;
    }
}

// ------------------------- fused w1|w3 GEMM (N=28672) -----------------------
__global__ __launch_bounds__(256, 4) void gemm_w13(const float* __restrict__ w1,
                                                   const float* __restrict__ w3) {
    const int KCH = 256;
    __shared__ __align__(16) unsigned long long xs[KCH][8];
    const int K = DM;
    int k0 = blockIdx.y * KCH;
#pragma unroll
    for (int b = 0; b < 8; ++b)
        for (int kk = threadIdx.x; kk < KCH; kk += 256)
            xs[kk][b] = dup_f32(g_xn[b * K + k0 + kk]);
    __syncthreads();

    int nc = blockIdx.x * 1024 + threadIdx.x * 4;
    const float* W;
    float* P;
    int nl;
    if (nc < HID) { W = w1; P = g_PA; nl = nc; }
    else          { W = w3; P = g_PB; nl = nc - HID; }

    unsigned long long a01[8], a23[8];
#pragma unroll
    for (int b = 0; b < 8; ++b) { a01[b] = 0ull; a23[b] = 0ull; }

    const float* wp = W + (size_t)k0 * HID + nl;
#pragma unroll 8
    for (int kk = 0; kk < KCH; ++kk) GEMM_KSTEP(wp, HID);

#pragma unroll
    for (int b = 0; b < 8; ++b) {
        ulonglong2 o;
        o.x = a01[b];
        o.y = a23[b];
        *(ulonglong2*)(P + ((size_t)blockIdx.y * 8 + b) * HID + nl) = o;
    }
}

// --------------- QKV combine (sum 64 partials) + RoPE, WIDE scalar-pair -----
// 192 blocks x 256 thr: thread = one (b, column-pair). Pairs keep the RoPE
// rotation local while quadrupling block-level parallelism vs float4/48blk.
__global__ void qkv_finish(const int* __restrict__ sp) {
    int p = blockIdx.x * 256 + threadIdx.x; // 24576 pairs
    int b = p / 3072;
    int r = p - b * 3072;
    int c0 = r * 2;
    float s0 = 0.f, s1 = 0.f;
#pragma unroll 8
    for (int ks = 0; ks < 64; ++ks) {
        const float2 v = *(const float2*)(g_PA + ((size_t)ks * 8 + b) * 6144 + c0);
        s0 += v.x;
        s1 += v.y;
    }
    int pos = *sp;
    if (c0 < 5120) {
        int cc = (c0 < 4096) ? c0 : c0 - 4096;
        int i0 = (cc & 127) >> 1;
        float if0 = powf(10000.0f, -(float)i0 * (1.0f / 64.0f));
        float sn, cs;
        sincosf((float)pos * if0, &sn, &cs);
        float o0 = s0 * cs - s1 * sn;
        float o1 = s0 * sn + s1 * cs;
        if (c0 < 4096) {
            g_xq[b * 4096 + c0] = o0;
            g_xq[b * 4096 + c0 + 1] = o1;
        } else {
            g_xk[b * 1024 + (c0 - 4096)] = o0;
            g_xk[b * 1024 + (c0 - 4096) + 1] = o1;
        }
    } else {
        g_xv[b * 1024 + (c0 - 5120)] = s0;
        g_xv[b * 1024 + (c0 - 5120) + 1] = s1;
    }
}

// --------------- attention partial, ACH=256, 256 thr, 512 blocks ------------
__global__ __launch_bounds__(256) void attn_part(const float* __restrict__ ck,
                                                 const float* __restrict__ cv,
                                                 const int* __restrict__ sp) {
    int chunk = blockIdx.x, kv = blockIdx.y, b = blockIdx.z;
    int pos = *sp;
    int L = pos + 1;
    int s0 = chunk * ACH;
    int tid = threadIdx.x;
    int w = tid >> 5, l = tid & 31;

    __shared__ float4 qs[4][32];
    __shared__ float4 sc4[ACH];
    __shared__ float Mh[4], Lh[4];
    __shared__ float4 vred[8][4][32];

    if (tid < 128) {
        int h = tid >> 5, q = tid & 31;
        qs[h][q] = *(const float4*)(g_xq + (((b << 5) + (kv << 2) + h) << 7) + q * 4);
    }
    __syncthreads();

    const float scale = 0.08838834764831845f;
    const float4* kbase = (const float4*)(ck + ((size_t)b * MSEQ) * (NKV * HD) + kv * HD);
    const float4* xkrow = (const float4*)(g_xk + (((b << 3) + kv) << 7));

    float4 qv0 = qs[0][l], qv1 = qs[1][l], qv2 = qs[2][l], qv3 = qs[3][l];

#pragma unroll
    for (int i = 0; i < ACH / 32; ++i) {
        int p0 = i * 32 + w;
        float4 k4[4];
#pragma unroll
        for (int j = 0; j < 4; ++j) {
            int s = s0 + p0 + j * 8;
            const float4* kr = (s == pos) ? xkrow : (kbase + (size_t)s * (NKV * HD / 4));
            k4[j] = (s < L) ? kr[l] : make_float4(0.f, 0.f, 0.f, 0.f);
        }
        float d[4][4];
#pragma unroll
        for (int j = 0; j < 4; ++j) {
            d[j][0] = k4[j].x * qv0.x + k4[j].y * qv0.y + k4[j].z * qv0.z + k4[j].w * qv0.w;
            d[j][1] = k4[j].x * qv1.x + k4[j].y * qv1.y + k4[j].z * qv1.z + k4[j].w * qv1.w;
            d[j][2] = k4[j].x * qv2.x + k4[j].y * qv2.y + k4[j].z * qv2.z + k4[j].w * qv2.w;
            d[j][3] = k4[j].x * qv3.x + k4[j].y * qv3.y + k4[j].z * qv3.z + k4[j].w * qv3.w;
        }
#pragma unroll
        for (int o = 16; o; o >>= 1) {
#pragma unroll
            for (int j = 0; j < 4; ++j) {
                d[j][0] += __shfl_xor_sync(0xffffffffu, d[j][0], o);
                d[j][1] += __shfl_xor_sync(0xffffffffu, d[j][1], o);
                d[j][2] += __shfl_xor_sync(0xffffffffu, d[j][2], o);
                d[j][3] += __shfl_xor_sync(0xffffffffu, d[j][3], o);
            }
        }
        if (l == 0) {
#pragma unroll
            for (int j = 0; j < 4; ++j) {
                int s = s0 + p0 + j * 8;
                sc4[p0 + j * 8] = (s < L)
                    ? make_float4(d[j][0] * scale, d[j][1] * scale,
                                  d[j][2] * scale, d[j][3] * scale)
                    : make_float4(-1e30f, -1e30f, -1e30f, -1e30f);
            }
        }
    }
    __syncthreads();

    if (w < 4) {
        const float* scf = (const float*)sc4;
        float v[8];
#pragma unroll
        for (int j = 0; j < 8; ++j) v[j] = scf[(l + 32 * j) * 4 + w];
        float m = v[0];
#pragma unroll
        for (int j = 1; j < 8; ++j) m = fmaxf(m, v[j]);
#pragma unroll
        for (int o = 16; o; o >>= 1) m = fmaxf(m, __shfl_xor_sync(0xffffffffu, m, o));
        float pj[8];
        float sum = 0.f;
#pragma unroll
        for (int j = 0; j < 8; ++j) {
            pj[j] = expf(v[j] - m);
            sum += pj[j];
        }
#pragma unroll
        for (int o = 16; o; o >>= 1) sum += __shfl_xor_sync(0xffffffffu, sum, o);
        float* scw = (float*)sc4;
#pragma unroll
        for (int j = 0; j < 8; ++j) scw[(l + 32 * j) * 4 + w] = pj[j];
        if (!l) { Mh[w] = m; Lh[w] = sum; }
    }
    __syncthreads();

    float4 a0 = make_float4(0.f, 0.f, 0.f, 0.f);
    float4 a1 = a0, a2 = a0, a3 = a0;
    int nc_ = pos - s0;
    if (nc_ > ACH) nc_ = ACH;
    if (nc_ < 0) nc_ = 0;
    const float4* vr = (const float4*)(cv + ((size_t)(b * MSEQ + s0)) * (NKV * HD) + kv * HD) + l;
#pragma unroll 8
    for (int ss = w; ss < nc_; ss += 8) {
        float4 v = vr[(size_t)ss * (NKV * HD / 4)];
        float4 p = sc4[ss];
        fma4(a0, p.x, v);
        fma4(a1, p.y, v);
        fma4(a2, p.z, v);
        fma4(a3, p.w, v);
    }
    int lp = pos - s0;
    if (lp >= 0 && lp < ACH && (lp & 7) == w) {
        float4 v = ((const float4*)(g_xv + (((b << 3) + kv) << 7)))[l];
        float4 p = sc4[lp];
        fma4(a0, p.x, v);
        fma4(a1, p.y, v);
        fma4(a2, p.z, v);
        fma4(a3, p.w, v);
    }
    vred[w][0][l] = a0;
    vred[w][1][l] = a1;
    vred[w][2][l] = a2;
    vred[w][3][l] = a3;
    __syncthreads();

    {
        int h = tid >> 6, j = tid & 63;
        float2 s2 = make_float2(0.f, 0.f);
#pragma unroll
        for (int ww = 0; ww < 8; ++ww) {
            float2 v = ((const float2*)vred[ww][h])[j];
            s2.x += v.x;
            s2.y += v.y;
        }
        int hg = (kv << 2) + h;
        *(float2*)(g_po + ((((size_t)(b << 5) + hg) << 3) + chunk) * HD + j * 2) = s2;
    }
    if (tid < 4) {
        int hg = (kv << 2) + tid;
        g_pm[(((b << 5) + hg) << 3) + chunk] = Mh[tid];
        g_pl[(((b << 5) + hg) << 3) + chunk] = Lh[tid];
    }
}

// --------------- attention: combine chunk partials ---------------------------
__global__ void attn_combine() {
    int h = blockIdx.x, b = blockIdx.y, d = threadIdx.x; // 128 threads
    int base = ((b << 5) + h) << 3;
    float M = -1e30f;
#pragma unroll
    for (int c = 0; c < NCHK; ++c) M = fmaxf(M, g_pm[base + c]);
    float Ls = 0.f, o = 0.f;
#pragma unroll
    for (int c = 0; c < NCHK; ++c) {
        float w = expf(g_pm[base + c] - M);
        Ls += g_pl[base + c] * w;
        o += g_po[(size_t)(base + c) * HD + d] * w;
    }
    g_attn[((b << 5) + h) * HD + d] = o / Ls;
}

// --------- combine partials + residual; stash per-colblock sumsq (WIDE) -----
__global__ void finish_res(int KS) {
    __shared__ float red[8];
    int b = blockIdx.y;
    int c = blockIdx.x * 256 + threadIdx.x; // grid.x = 16 -> 4096 cols
    float s = g_h[b * DM + c];
#pragma unroll 8
    for (int ks = 0; ks < KS; ++ks) s += g_PA[((size_t)ks * 8 + b) * DM + c];
    g_h[b * DM + c] = s;
    float sq = s * s;
    int lane = threadIdx.x & 31, wid = threadIdx.x >> 5;
#pragma unroll
    for (int o = 16; o; o >>= 1) sq += __shfl_xor_sync(0xffffffffu, sq, o);
    if (!lane) red[wid] = sq;
    __syncthreads();
    if (threadIdx.x == 0) {
        float t = 0.f;
#pragma unroll
        for (int ww = 0; ww < 8; ++ww) t += red[ww];
        g_bsq[b * 16 + blockIdx.x] = t;
    }
}

// --------------- rmsnorm using stashed sums (WIDE) --------------------------
__global__ void finish_norm(const float* __restrict__ gamma) {
    int b = blockIdx.y;
    int c = blockIdx.x * 256 + threadIdx.x;
    float sq = 0.f;
#pragma unroll
    for (int i = 0; i < 16; ++i) sq += g_bsq[b * 16 + i];
    float rn = rsqrtf(sq * (1.0f / DM));
    g_xn[b * DM + c] = g_h[b * DM + c] * rn * gamma[c];
}

// --------------- ffn gate: g = silu(x@w1) * (x@w3), WIDE scalar --------------
// 448 blocks x 256 thr: thread = one (b, column).
__global__ void ffn_act(int KS) {
    int p = blockIdx.x * 256 + threadIdx.x; // 114688 slots
    int b = p / HID;
    int c = p - b * HID;
    float s1 = 0.f, s3 = 0.f;
#pragma unroll 8
    for (int ks = 0; ks < KS; ++ks) {
        s1 += g_PA[((size_t)ks * 8 + b) * HID + c];
        s3 += g_PB[((size_t)ks * 8 + b) * HID + c];
    }
    float sig = 1.0f / (1.0f + expf(-s1));
    g_g[b * HID + c] = s1 * sig * s3;
}

// --------------- logits combine, float4 --------------------------------------
__global__ void wout_finish(float* __restrict__ out, int KS) {
    int b = blockIdx.y;
    int c4 = blockIdx.x * 256 + threadIdx.x;
    if (c4 >= VOC / 4) return;
    int c = c4 * 4;
    float4 s = make_float4(0.f, 0.f, 0.f, 0.f);
#pragma unroll 4
    for (int ks = 0; ks < KS; ++ks) {
        float4 v = *(const float4*)(g_PA + ((size_t)ks * 8 + b) * VOC + c);
        s.x += v.x; s.y += v.y; s.z += v.z; s.w += v.w;
    }
    *(float4*)(out + b * VOC + c) = s;
}

// ------------------------- launch --------------------------------------------
extern "C" void kernel_launch(void* const* d_in, const int* in_sizes, int n_in,
                              void* d_out, int out_size) {
    const int* tokens = (const int*)d_in[0];
    const int* sp = (const int*)d_in[1];
    const float* emb = (const float*)d_in[2];
    const float* g1 = (const float*)d_in[3];
    const float* g2 = (const float*)d_in[4];
    const float* gf = (const float*)d_in[5];
    const float* wq = (const float*)d_in[6];
    const float* wk = (const float*)d_in[7];
    const float* wv = (const float*)d_in[8];
    const float* wo = (const float*)d_in[9];
    const float* w1 = (const float*)d_in[10];
    const float* w2 = (const float*)d_in[11];
    const float* w3 = (const float*)d_in[12];
    const float* wout = (const float*)d_in[13];
    const float* ck = (const float*)d_in[14];
    const float* cv = (const float*)d_in[15];
    float* out = (float*)d_out;

    embed_norm<<<8, 256>>>(tokens, emb, g1);
    // QKV: KS=64, kchunk=64 -> 384 blocks
    gemm_qkv<<<dim3(6, 64), 256>>>(wq, wk, wv);
    qkv_finish<<<96, 256>>>(sp);
    // attention: 8 chunks x 8 kv x 8 batch = 512 blocks (single wave)
    attn_part<<<dim3(NCHK, 8, 8), 256>>>(ck, cv, sp);
    attn_combine<<<dim3(32, 8), 128>>>();
    // wo: KS=128, kchunk=32 -> 512 blocks (3.46/SM)
    gemm8<1, 0, 32><<<dim3(4, 128), 256>>>(wo, 4096, 4096);
    finish_res<<<dim3(16, 8), 256>>>(128);
    finish_norm<<<dim3(16, 8), 256>>>(g2);
    // w1|w3 fused: KS=16, kchunk=256 -> 448 blocks
    gemm_w13<<<dim3(28, 16), 256>>>(w1, w3);
    ffn_act<<<448, 256>>>(16);
    // w2: KS=128, kchunk=112 -> 512 blocks (3.46/SM)
    gemm8<2, 0, 112><<<dim3(4, 128), 256>>>(w2, 14336, 4096);
    finish_res<<<dim3(16, 8), 256>>>(128);
    finish_norm<<<dim3(16, 8), 256>>>(gf);
    // w_out: KS=16, kchunk=256 -> 512 blocks
    gemm8<0, 0, 256><<<dim3(32, 16), 256>>>(wout, 4096, 32000);
    wout_finish<<<dim3(32, 8), 256>>>(out, 16);
}

// round 17
// speedup vs baseline: 1.3242x; 1.0090x over previous
#include <cuda_runtime.h>
#include <cuda_bf16.h>
#include <math.h>

// ---------------------------------------------------------------------------
// Llama-style decode step, BATCH=8, S=1. R16 champion (311.1us) + R17:
// attn_part prefetches V rows into L2 during the score phase (same warp
// consumes them after the softmax barrier).
// GEMVs: f32x2 FMA, 4 cols/thread, 256 thr, (256,4) bounds, unroll-8,
// coalesced per-b X staging, .cs weights only (partials L2-default).
// ---------------------------------------------------------------------------

#define DM 4096
#define NH 32
#define NKV 8
#define HD 128
#define HID 14336
#define VOC 32000
#define MSEQ 2048
#define B8 8
#define ACH 256   // attention chunk length
#define NCHK 8    // MSEQ / ACH

// ------------------------- scratch (device globals) -------------------------
__device__ float g_h[B8 * DM];
__device__ float g_xn[B8 * DM];
__device__ float g_xq[B8 * NH * HD];
__device__ float g_xk[B8 * NKV * HD];
__device__ float g_xv[B8 * NKV * HD];
__device__ float g_pm[B8 * NH * NCHK];
__device__ float g_pl[B8 * NH * NCHK];
__device__ float g_po[B8 * NH * NCHK * HD];
__device__ float g_attn[B8 * DM];
__device__ float g_g[B8 * HID];
__device__ float g_bsq[B8 * 16];
__device__ float g_PA[16 * 8 * 32000];
__device__ float g_PB[16 * 8 * 14336];

// ------------------------- helpers -------------------------
__device__ __forceinline__ void fma4(float4& a, float s, const float4& w) {
    a.x = fmaf(s, w.x, a.x);
    a.y = fmaf(s, w.y, a.y);
    a.z = fmaf(s, w.z, a.z);
    a.w = fmaf(s, w.w, a.w);
}

__device__ __forceinline__ unsigned long long dup_f32(float v) {
    unsigned long long pv;
    asm("mov.b64 %0, {%1, %1};" : "=l"(pv) : "f"(v));
    return pv;
}

// -------- GEMM inner macro: 1 LDG.128(.cs) + 4 LDS.128 + 16 FFMA2 per k -----
#define GEMM_KSTEP(wp, stride)                                                 \
    {                                                                          \
        ulonglong2 w2;                                                         \
        asm("ld.global.cs.v2.u64 {%0,%1}, [%2];"                               \
            : "=l"(w2.x), "=l"(w2.y) : "l"(wp));                               \
        (wp) += (stride);                                                      \
        _Pragma("unroll") for (int p = 0; p < 4; ++p) {                        \
            ulonglong2 xp = *(const ulonglong2*)&xs[kk][2 * p];                \
            asm("fma.rn.f32x2 %0, %4, %6, %0;\n\t"                             \
                "fma.rn.f32x2 %1, %4, %7, %1;\n\t"                             \
                "fma.rn.f32x2 %2, %5, %6, %2;\n\t"                             \
                "fma.rn.f32x2 %3, %5, %7, %3;"                                 \
                : "+l"(a01[2 * p]), "+l"(a23[2 * p]),                          \
                  "+l"(a01[2 * p + 1]), "+l"(a23[2 * p + 1])                   \
                : "l"(xp.x), "l"(xp.y), "l"(w2.x), "l"(w2.y));                 \
        }                                                                      \
    }

// ------------------------- kernel 0: embed + rmsnorm(gamma1) ----------------
__global__ void embed_norm(const int* __restrict__ tokens,
                           const float* __restrict__ emb,
                           const float* __restrict__ gamma) {
    __shared__ float red[8];
    int b = blockIdx.x;
    int tok = tokens[b];
    const float* row = emb + (size_t)tok * DM;
    float loc[16];
    float sq = 0.f;
#pragma unroll
    for (int i = 0; i < 16; ++i) {
        float v = row[threadIdx.x + i * 256];
        loc[i] = v;
        sq += v * v;
    }
    int lane = threadIdx.x & 31, wid = threadIdx.x >> 5;
#pragma unroll
    for (int o = 16; o; o >>= 1) sq += __shfl_xor_sync(0xffffffffu, sq, o);
    if (!lane) red[wid] = sq;
    __syncthreads();
    float tot = 0.f;
#pragma unroll
    for (int w = 0; w < 8; ++w) tot += red[w];
    float rn = rsqrtf(tot * (1.0f / DM));
#pragma unroll
    for (int i = 0; i < 16; ++i) {
        int c = threadIdx.x + i * 256;
        g_h[b * DM + c] = loc[i];
        g_xn[b * DM + c] = loc[i] * rn * gamma[c];
    }
}

// ------------------------- generic split-K GEMM (M=8), f32x2 ----------------
// XSEL: 0 = g_xn, 1 = g_attn, 2 = g_g.  PSEL: 0 = g_PA, 1 = g_PB.
template <int XSEL, int PSEL, int KCH>
__global__ __launch_bounds__(256, 4) void gemm8(const float* __restrict__ W,
                                                int K, int N) {
    const float* X = (XSEL == 0) ? g_xn : (XSEL == 1) ? g_attn : g_g;
    float* P = (PSEL == 0) ? g_PA : g_PB;

    __shared__ __align__(16) unsigned long long xs[KCH][8];

    int k0 = blockIdx.y * KCH;
#pragma unroll
    for (int b = 0; b < 8; ++b)
        for (int kk = threadIdx.x; kk < KCH; kk += 256)
            xs[kk][b] = dup_f32(X[b * K + k0 + kk]);
    __syncthreads();

    int n0 = blockIdx.x * 1024 + threadIdx.x * 4;
    if (n0 >= N) return;

    unsigned long long a01[8], a23[8];
#pragma unroll
    for (int b = 0; b < 8; ++b) { a01[b] = 0ull; a23[b] = 0ull; }

    const float* wp = W + (size_t)k0 * N + n0;
#pragma unroll 8
    for (int kk = 0; kk < KCH; ++kk) GEMM_KSTEP(wp, N);

#pragma unroll
    for (int b = 0; b < 8; ++b) {
        ulonglong2 o;
        o.x = a01[b];
        o.y = a23[b];
        *(ulonglong2*)(P + ((size_t)blockIdx.y * 8 + b) * N + n0) = o;
    }
}

// ------------------------- fused QKV GEMM (concat N=6144) -------------------
__global__ __launch_bounds__(256, 4) void gemm_qkv(const float* __restrict__ wq,
                                                   const float* __restrict__ wk,
                                                   const float* __restrict__ wv) {
    const int KCH = 64;   // KS=64 -> 384 blocks
    __shared__ __align__(16) unsigned long long xs[KCH][8];
    const int K = DM;
    int k0 = blockIdx.y * KCH;
#pragma unroll
    for (int b = 0; b < 8; ++b)
        for (int kk = threadIdx.x; kk < KCH; kk += 256)
            xs[kk][b] = dup_f32(g_xn[b * K + k0 + kk]);
    __syncthreads();

    int nc = blockIdx.x * 1024 + threadIdx.x * 4;
    const float* W;
    int Nw, nl;
    if (nc < 4096)      { W = wq; Nw = 4096; nl = nc; }
    else if (nc < 5120) { W = wk; Nw = 1024; nl = nc - 4096; }
    else                { W = wv; Nw = 1024; nl = nc - 5120; }

    unsigned long long a01[8], a23[8];
#pragma unroll
    for (int b = 0; b < 8; ++b) { a01[b] = 0ull; a23[b] = 0ull; }

    const float* wp = W + (size_t)k0 * Nw + nl;
#pragma unroll 8
    for (int kk = 0; kk < KCH; ++kk) GEMM_KSTEP(wp, Nw);

#pragma unroll
    for (int b = 0; b < 8; ++b) {
        ulonglong2 o;
        o.x = a01[b];
        o.y = a23[b];
        *(ulonglong2*)(g_PA + ((size_t)blockIdx.y * 8 + b) * 6144 + nc) = o;
    }
}

// ------------------------- fused w1|w3 GEMM (N=28672) -----------------------
__global__ __launch_bounds__(256, 4) void gemm_w13(const float* __restrict__ w1,
                                                   const float* __restrict__ w3) {
    const int KCH = 256;
    __shared__ __align__(16) unsigned long long xs[KCH][8];
    const int K = DM;
    int k0 = blockIdx.y * KCH;
#pragma unroll
    for (int b = 0; b < 8; ++b)
        for (int kk = threadIdx.x; kk < KCH; kk += 256)
            xs[kk][b] = dup_f32(g_xn[b * K + k0 + kk]);
    __syncthreads();

    int nc = blockIdx.x * 1024 + threadIdx.x * 4;
    const float* W;
    float* P;
    int nl;
    if (nc < HID) { W = w1; P = g_PA; nl = nc; }
    else          { W = w3; P = g_PB; nl = nc - HID; }

    unsigned long long a01[8], a23[8];
#pragma unroll
    for (int b = 0; b < 8; ++b) { a01[b] = 0ull; a23[b] = 0ull; }

    const float* wp = W + (size_t)k0 * HID + nl;
#pragma unroll 8
    for (int kk = 0; kk < KCH; ++kk) GEMM_KSTEP(wp, HID);

#pragma unroll
    for (int b = 0; b < 8; ++b) {
        ulonglong2 o;
        o.x = a01[b];
        o.y = a23[b];
        *(ulonglong2*)(P + ((size_t)blockIdx.y * 8 + b) * HID + nl) = o;
    }
}

// --------------- QKV combine (sum 64 partials) + RoPE, WIDE scalar-pair -----
__global__ void qkv_finish(const int* __restrict__ sp) {
    int p = blockIdx.x * 256 + threadIdx.x; // 24576 pairs
    int b = p / 3072;
    int r = p - b * 3072;
    int c0 = r * 2;
    float s0 = 0.f, s1 = 0.f;
#pragma unroll 8
    for (int ks = 0; ks < 64; ++ks) {
        const float2 v = *(const float2*)(g_PA + ((size_t)ks * 8 + b) * 6144 + c0);
        s0 += v.x;
        s1 += v.y;
    }
    int pos = *sp;
    if (c0 < 5120) {
        int cc = (c0 < 4096) ? c0 : c0 - 4096;
        int i0 = (cc & 127) >> 1;
        float if0 = powf(10000.0f, -(float)i0 * (1.0f / 64.0f));
        float sn, cs;
        sincosf((float)pos * if0, &sn, &cs);
        float o0 = s0 * cs - s1 * sn;
        float o1 = s0 * sn + s1 * cs;
        if (c0 < 4096) {
            g_xq[b * 4096 + c0] = o0;
            g_xq[b * 4096 + c0 + 1] = o1;
        } else {
            g_xk[b * 1024 + (c0 - 4096)] = o0;
            g_xk[b * 1024 + (c0 - 4096) + 1] = o1;
        }
    } else {
        g_xv[b * 1024 + (c0 - 5120)] = s0;
        g_xv[b * 1024 + (c0 - 5120) + 1] = s1;
    }
}

// --------------- attention partial, ACH=256, 256 thr, 512 blocks ------------
// R17: score phase prefetches this warp's V rows into L2 (consumed by the
// same warp in the V pass after the softmax barrier).
__global__ __launch_bounds__(256) void attn_part(const float* __restrict__ ck,
                                                 const float* __restrict__ cv,
                                                 const int* __restrict__ sp) {
    int chunk = blockIdx.x, kv = blockIdx.y, b = blockIdx.z;
    int pos = *sp;
    int L = pos + 1;
    int s0 = chunk * ACH;
    int tid = threadIdx.x;
    int w = tid >> 5, l = tid & 31;

    __shared__ float4 qs[4][32];
    __shared__ float4 sc4[ACH];
    __shared__ float Mh[4], Lh[4];
    __shared__ float4 vred[8][4][32];

    if (tid < 128) {
        int h = tid >> 5, q = tid & 31;
        qs[h][q] = *(const float4*)(g_xq + (((b << 5) + (kv << 2) + h) << 7) + q * 4);
    }
    __syncthreads();

    const float scale = 0.08838834764831845f;
    const float4* kbase = (const float4*)(ck + ((size_t)b * MSEQ) * (NKV * HD) + kv * HD);
    const float4* xkrow = (const float4*)(g_xk + (((b << 3) + kv) << 7));
    const float4* vr = (const float4*)(cv + ((size_t)(b * MSEQ + s0)) * (NKV * HD) + kv * HD) + l;

    float4 qv0 = qs[0][l], qv1 = qs[1][l], qv2 = qs[2][l], qv3 = qs[3][l];

#pragma unroll
    for (int i = 0; i < ACH / 32; ++i) {
        int p0 = i * 32 + w;
        float4 k4[4];
#pragma unroll
        for (int j = 0; j < 4; ++j) {
            int s = s0 + p0 + j * 8;
            const float4* kr = (s == pos) ? xkrow : (kbase + (size_t)s * (NKV * HD / 4));
            k4[j] = (s < L) ? kr[l] : make_float4(0.f, 0.f, 0.f, 0.f);
            // Prefetch this warp's V row for position p0+j*8 into L2
            // (always within cache_v: s0+p0+j*8 < MSEQ).
            asm volatile("prefetch.global.L2 [%0];"
                         :: "l"(vr + (size_t)(p0 + j * 8) * (NKV * HD / 4)));
        }
        float d[4][4];
#pragma unroll
        for (int j = 0; j < 4; ++j) {
            d[j][0] = k4[j].x * qv0.x + k4[j].y * qv0.y + k4[j].z * qv0.z + k4[j].w * qv0.w;
            d[j][1] = k4[j].x * qv1.x + k4[j].y * qv1.y + k4[j].z * qv1.z + k4[j].w * qv1.w;
            d[j][2] = k4[j].x * qv2.x + k4[j].y * qv2.y + k4[j].z * qv2.z + k4[j].w * qv2.w;
            d[j][3] = k4[j].x * qv3.x + k4[j].y * qv3.y + k4[j].z * qv3.z + k4[j].w * qv3.w;
        }
#pragma unroll
        for (int o = 16; o; o >>= 1) {
#pragma unroll
            for (int j = 0; j < 4; ++j) {
                d[j][0] += __shfl_xor_sync(0xffffffffu, d[j][0], o);
                d[j][1] += __shfl_xor_sync(0xffffffffu, d[j][1], o);
                d[j][2] += __shfl_xor_sync(0xffffffffu, d[j][2], o);
                d[j][3] += __shfl_xor_sync(0xffffffffu, d[j][3], o);
            }
        }
        if (l == 0) {
#pragma unroll
            for (int j = 0; j < 4; ++j) {
                int s = s0 + p0 + j * 8;
                sc4[p0 + j * 8] = (s < L)
                    ? make_float4(d[j][0] * scale, d[j][1] * scale,
                                  d[j][2] * scale, d[j][3] * scale)
                    : make_float4(-1e30f, -1e30f, -1e30f, -1e30f);
            }
        }
    }
    __syncthreads();

    if (w < 4) {
        const float* scf = (const float*)sc4;
        float v[8];
#pragma unroll
        for (int j = 0; j < 8; ++j) v[j] = scf[(l + 32 * j) * 4 + w];
        float m = v[0];
#pragma unroll
        for (int j = 1; j < 8; ++j) m = fmaxf(m, v[j]);
#pragma unroll
        for (int o = 16; o; o >>= 1) m = fmaxf(m, __shfl_xor_sync(0xffffffffu, m, o));
        float pj[8];
        float sum = 0.f;
#pragma unroll
        for (int j = 0; j < 8; ++j) {
            pj[j] = expf(v[j] - m);
            sum += pj[j];
        }
#pragma unroll
        for (int o = 16; o; o >>= 1) sum += __shfl_xor_sync(0xffffffffu, sum, o);
        float* scw = (float*)sc4;
#pragma unroll
        for (int j = 0; j < 8; ++j) scw[(l + 32 * j) * 4 + w] = pj[j];
        if (!l) { Mh[w] = m; Lh[w] = sum; }
    }
    __syncthreads();

    float4 a0 = make_float4(0.f, 0.f, 0.f, 0.f);
    float4 a1 = a0, a2 = a0, a3 = a0;
    int nc_ = pos - s0;
    if (nc_ > ACH) nc_ = ACH;
    if (nc_ < 0) nc_ = 0;
#pragma unroll 8
    for (int ss = w; ss < nc_; ss += 8) {
        float4 v = vr[(size_t)ss * (NKV * HD / 4)];
        float4 p = sc4[ss];
        fma4(a0, p.x, v);
        fma4(a1, p.y, v);
        fma4(a2, p.z, v);
        fma4(a3, p.w, v);
    }
    int lp = pos - s0;
    if (lp >= 0 && lp < ACH && (lp & 7) == w) {
        float4 v = ((const float4*)(g_xv + (((b << 3) + kv) << 7)))[l];
        float4 p = sc4[lp];
        fma4(a0, p.x, v);
        fma4(a1, p.y, v);
        fma4(a2, p.z, v);
        fma4(a3, p.w, v);
    }
    vred[w][0][l] = a0;
    vred[w][1][l] = a1;
    vred[w][2][l] = a2;
    vred[w][3][l] = a3;
    __syncthreads();

    {
        int h = tid >> 6, j = tid & 63;
        float2 s2 = make_float2(0.f, 0.f);
#pragma unroll
        for (int ww = 0; ww < 8; ++ww) {
            float2 v = ((const float2*)vred[ww][h])[j];
            s2.x += v.x;
            s2.y += v.y;
        }
        int hg = (kv << 2) + h;
        *(float2*)(g_po + ((((size_t)(b << 5) + hg) << 3) + chunk) * HD + j * 2) = s2;
    }
    if (tid < 4) {
        int hg = (kv << 2) + tid;
        g_pm[(((b << 5) + hg) << 3) + chunk] = Mh[tid];
        g_pl[(((b << 5) + hg) << 3) + chunk] = Lh[tid];
    }
}

// --------------- attention: combine chunk partials ---------------------------
__global__ void attn_combine() {
    int h = blockIdx.x, b = blockIdx.y, d = threadIdx.x; // 128 threads
    int base = ((b << 5) + h) << 3;
    float M = -1e30f;
#pragma unroll
    for (int c = 0; c < NCHK; ++c) M = fmaxf(M, g_pm[base + c]);
    float Ls = 0.f, o = 0.f;
#pragma unroll
    for (int c = 0; c < NCHK; ++c) {
        float w = expf(g_pm[base + c] - M);
        Ls += g_pl[base + c] * w;
        o += g_po[(size_t)(base + c) * HD + d] * w;
    }
    g_attn[((b << 5) + h) * HD + d] = o / Ls;
}

// --------- combine partials + residual; stash per-colblock sumsq (WIDE) -----
__global__ void finish_res(int KS) {
    __shared__ float red[8];
    int b = blockIdx.y;
    int c = blockIdx.x * 256 + threadIdx.x; // grid.x = 16 -> 4096 cols
    float s = g_h[b * DM + c];
#pragma unroll 8
    for (int ks = 0; ks < KS; ++ks) s += g_PA[((size_t)ks * 8 + b) * DM + c];
    g_h[b * DM + c] = s;
    float sq = s * s;
    int lane = threadIdx.x & 31, wid = threadIdx.x >> 5;
#pragma unroll
    for (int o = 16; o; o >>= 1) sq += __shfl_xor_sync(0xffffffffu, sq, o);
    if (!lane) red[wid] = sq;
    __syncthreads();
    if (threadIdx.x == 0) {
        float t = 0.f;
#pragma unroll
        for (int ww = 0; ww < 8; ++ww) t += red[ww];
        g_bsq[b * 16 + blockIdx.x] = t;
    }
}

// --------------- rmsnorm using stashed sums (WIDE) --------------------------
__global__ void finish_norm(const float* __restrict__ gamma) {
    int b = blockIdx.y;
    int c = blockIdx.x * 256 + threadIdx.x;
    float sq = 0.f;
#pragma unroll
    for (int i = 0; i < 16; ++i) sq += g_bsq[b * 16 + i];
    float rn = rsqrtf(sq * (1.0f / DM));
    g_xn[b * DM + c] = g_h[b * DM + c] * rn * gamma[c];
}

// --------------- ffn gate: g = silu(x@w1) * (x@w3), WIDE scalar --------------
__global__ void ffn_act(int KS) {
    int p = blockIdx.x * 256 + threadIdx.x; // 114688 slots
    int b = p / HID;
    int c = p - b * HID;
    float s1 = 0.f, s3 = 0.f;
#pragma unroll 8
    for (int ks = 0; ks < KS; ++ks) {
        s1 += g_PA[((size_t)ks * 8 + b) * HID + c];
        s3 += g_PB[((size_t)ks * 8 + b) * HID + c];
    }
    float sig = 1.0f / (1.0f + expf(-s1));
    g_g[b * HID + c] = s1 * sig * s3;
}

// --------------- logits combine, float4 --------------------------------------
__global__ void wout_finish(float* __restrict__ out, int KS) {
    int b = blockIdx.y;
    int c4 = blockIdx.x * 256 + threadIdx.x;
    if (c4 >= VOC / 4) return;
    int c = c4 * 4;
    float4 s = make_float4(0.f, 0.f, 0.f, 0.f);
#pragma unroll 4
    for (int ks = 0; ks < KS; ++ks) {
        float4 v = *(const float4*)(g_PA + ((size_t)ks * 8 + b) * VOC + c);
        s.x += v.x; s.y += v.y; s.z += v.z; s.w += v.w;
    }
    *(float4*)(out + b * VOC + c) = s;
}

// ------------------------- launch --------------------------------------------
extern "C" void kernel_launch(void* const* d_in, const int* in_sizes, int n_in,
                              void* d_out, int out_size) {
    const int* tokens = (const int*)d_in[0];
    const int* sp = (const int*)d_in[1];
    const float* emb = (const float*)d_in[2];
    const float* g1 = (const float*)d_in[3];
    const float* g2 = (const float*)d_in[4];
    const float* gf = (const float*)d_in[5];
    const float* wq = (const float*)d_in[6];
    const float* wk = (const float*)d_in[7];
    const float* wv = (const float*)d_in[8];
    const float* wo = (const float*)d_in[9];
    const float* w1 = (const float*)d_in[10];
    const float* w2 = (const float*)d_in[11];
    const float* w3 = (const float*)d_in[12];
    const float* wout = (const float*)d_in[13];
    const float* ck = (const float*)d_in[14];
    const float* cv = (const float*)d_in[15];
    float* out = (float*)d_out;

    embed_norm<<<8, 256>>>(tokens, emb, g1);
    // QKV: KS=64, kchunk=64 -> 384 blocks
    gemm_qkv<<<dim3(6, 64), 256>>>(wq, wk, wv);
    qkv_finish<<<96, 256>>>(sp);
    // attention: 8 chunks x 8 kv x 8 batch = 512 blocks (single wave)
    attn_part<<<dim3(NCHK, 8, 8), 256>>>(ck, cv, sp);
    attn_combine<<<dim3(32, 8), 128>>>();
    // wo: KS=128, kchunk=32 -> 512 blocks (3.46/SM)
    gemm8<1, 0, 32><<<dim3(4, 128), 256>>>(wo, 4096, 4096);
    finish_res<<<dim3(16, 8), 256>>>(128);
    finish_norm<<<dim3(16, 8), 256>>>(g2);
    // w1|w3 fused: KS=16, kchunk=256 -> 448 blocks
    gemm_w13<<<dim3(28, 16), 256>>>(w1, w3);
    ffn_act<<<448, 256>>>(16);
    // w2: KS=128, kchunk=112 -> 512 blocks (3.46/SM)
    gemm8<2, 0, 112><<<dim3(4, 128), 256>>>(w2, 14336, 4096);
    finish_res<<<dim3(16, 8), 256>>>(128);
    finish_norm<<<dim3(16, 8), 256>>>(gf);
    // w_out: KS=16, kchunk=256 -> 512 blocks
    gemm8<0, 0, 256><<<dim3(32, 16), 256>>>(wout, 4096, 32000);
    wout_finish<<<dim3(32, 8), 256>>>(out, 16);
}